// round 5
// baseline (speedup 1.0000x reference)
#include <cuda_runtime.h>
#include <math.h>

// ----- problem constants -----
#define BB 64      // batch
#define TE 128     // encoder timesteps
#define TD 64      // decoder timesteps
#define DE 512     // embedding dim
#define DH 1024    // hidden dim (enc & dec)
#define H3 3072    // 3 * DH
#define VV 32000   // vocab
#define DIN (DE + DH) // decoder input dim = 1536

// ----- scratch (static device globals; no allocation allowed) -----
__device__ float g_xe[(size_t)TE * BB * DE];      // gathered encoder embeddings, t-major rows
__device__ float g_gi_enc[(size_t)TE * BB * H3];  // precomputed encoder input gates
__device__ float g_wdec[(size_t)TD * BB * DE];    // gathered decoder word embeddings
__device__ float g_gi_dec[(size_t)TD * BB * H3];  // precomputed decoder word input gates
__device__ float g_gi_ctx[(size_t)BB * H3];       // context contribution (time-invariant)
__device__ float g_hA[BB * DH];
__device__ float g_hB[BB * DH];
__device__ float g_states[(size_t)BB * TD * DH];  // (B, T_dec, DH) row-major

// ===================== gather kernels =====================

__global__ void gather_enc(const int* __restrict__ x, const float* __restrict__ emb,
                           float* __restrict__ out)
{
    // row r = t*B + b ; copy 512 floats (128 float4) per row
    int r = blockIdx.x;
    int t = r >> 6;          // / BB
    int b = r & 63;
    int tok = x[b * TE + t];
    const float4* s = (const float4*)(emb + (size_t)tok * DE);
    float4* d = (float4*)(out + (size_t)r * DE);
    d[threadIdx.x] = s[threadIdx.x];
}

__global__ void gather_dec(const int* __restrict__ labels, const int* __restrict__ bos,
                           const float* __restrict__ emb, float* __restrict__ out)
{
    int r = blockIdx.x;
    int t = r >> 6;
    int b = r & 63;
    int tok = (t == 0) ? bos[0] : labels[b * TD + t - 1];
    const float4* s = (const float4*)(emb + (size_t)tok * DE);
    float4* d = (float4*)(out + (size_t)r * DE);
    d[threadIdx.x] = s[threadIdx.x];
}

__global__ void set_h(float* __restrict__ dst, const float* __restrict__ src)
{
    int i = blockIdx.x * 1024 + threadIdx.x;   // grid 64 x 1024 = 65536
    dst[i] = src ? src[i & (DH - 1)] : 0.0f;
}

// ===================== generic SGEMM-NT =====================
// C[M,N] = A[M,K](row, lda) * B[N,K](row, ldb)^T + bias[N]
// BM=BN=128, BK=16, 256 threads, 8x8 microtile (4+4 split for bank-conflict-free LDS.128)
// Requires: N % 128 == 0, K % 16 == 0, pointers 16B-aligned, lda/ldb % 4 == 0.

__global__ __launch_bounds__(256) void sgemm_nt(
    const float* __restrict__ A, const float* __restrict__ Bm,
    const float* __restrict__ bias, float* __restrict__ C,
    int M, int N, int K, int lda, int ldb)
{
    __shared__ float As[16][132];
    __shared__ float Bs[16][132];

    const int t  = threadIdx.x;
    const int tx = t & 15;
    const int ty = t >> 4;
    const int row0 = blockIdx.y * 128;
    const int col0 = blockIdx.x * 128;

    float acc[8][8];
#pragma unroll
    for (int i = 0; i < 8; i++)
#pragma unroll
        for (int j = 0; j < 8; j++) acc[i][j] = 0.0f;

    for (int k0 = 0; k0 < K; k0 += 16) {
#pragma unroll
        for (int r = 0; r < 2; r++) {
            int id = t + 256 * r;
            int ar = id >> 2;        // 0..127
            int kq = id & 3;         // 0..3  (float4 within the 16-wide k tile)
            // A tile (guard rows against M)
            float4 v = make_float4(0.f, 0.f, 0.f, 0.f);
            int gr = row0 + ar;
            if (gr < M) v = *(const float4*)(A + (size_t)gr * lda + k0 + kq * 4);
            As[kq * 4 + 0][ar] = v.x;
            As[kq * 4 + 1][ar] = v.y;
            As[kq * 4 + 2][ar] = v.z;
            As[kq * 4 + 3][ar] = v.w;
            // B tile (N always a multiple of 128 -> no guard)
            float4 wv = *(const float4*)(Bm + (size_t)(col0 + ar) * ldb + k0 + kq * 4);
            Bs[kq * 4 + 0][ar] = wv.x;
            Bs[kq * 4 + 1][ar] = wv.y;
            Bs[kq * 4 + 2][ar] = wv.z;
            Bs[kq * 4 + 3][ar] = wv.w;
        }
        __syncthreads();

#pragma unroll
        for (int k = 0; k < 16; k++) {
            float4 a0 = *(const float4*)&As[k][ty * 4];
            float4 a1 = *(const float4*)&As[k][ty * 4 + 64];
            float4 b0 = *(const float4*)&Bs[k][tx * 4];
            float4 b1 = *(const float4*)&Bs[k][tx * 4 + 64];
            float av[8] = {a0.x, a0.y, a0.z, a0.w, a1.x, a1.y, a1.z, a1.w};
            float bv[8] = {b0.x, b0.y, b0.z, b0.w, b1.x, b1.y, b1.z, b1.w};
#pragma unroll
            for (int i = 0; i < 8; i++)
#pragma unroll
                for (int j = 0; j < 8; j++) acc[i][j] += av[i] * bv[j];
        }
        __syncthreads();
    }

    // epilogue
    float bc[8];
#pragma unroll
    for (int j = 0; j < 8; j++) {
        int cj = col0 + ((j < 4) ? (tx * 4 + j) : (64 + tx * 4 + j - 4));
        bc[j] = bias ? bias[cj] : 0.0f;
    }
#pragma unroll
    for (int i = 0; i < 8; i++) {
        int ri = row0 + ((i < 4) ? (ty * 4 + i) : (64 + ty * 4 + i - 4));
        if (ri < M) {
            float4 o0 = make_float4(acc[i][0] + bc[0], acc[i][1] + bc[1],
                                    acc[i][2] + bc[2], acc[i][3] + bc[3]);
            float4 o1 = make_float4(acc[i][4] + bc[4], acc[i][5] + bc[5],
                                    acc[i][6] + bc[6], acc[i][7] + bc[7]);
            *(float4*)(C + (size_t)ri * N + col0 + tx * 4)      = o0;
            *(float4*)(C + (size_t)ri * N + col0 + 64 + tx * 4) = o1;
        }
    }
}

// ===================== fused GRU step =====================
// One CTA handles ALL 64 batch rows and 8 hidden columns j (=> 24 Whh rows: r/z/n gates),
// so Whh is streamed from L2 exactly once per step across the grid.
// grid = DH/8 = 128 CTAs, 128 threads (4 warps; warp w owns j = jb + 2w, jb + 2w + 1).
// Thread owns batch rows (lane, lane+32). Fully fused gate epilogue, no atomics.

__global__ __launch_bounds__(128) void gru_step(
    const float* __restrict__ gi,    // (B,H3) input-gate preactivations at this t (incl. bih)
    const float* __restrict__ gi2,   // optional second term (decoder ctx), or nullptr
    const float* __restrict__ Whh,   // (H3, DH) row-major
    const float* __restrict__ bhh,   // (H3)
    const float* __restrict__ h_in,  // (B, DH)
    float* __restrict__ h_out,       // (B, DH)
    float* __restrict__ st_out,      // optional: states base + t*DH; index b*st_stride + j
    int st_stride)
{
    __shared__ float hs[64][68];   // h tile, [b][k], row stride 68 => conflict-free LDS.128
    __shared__ float ws[24][68];   // Whh rows for this CTA's 8 j's x 3 gates

    const int tid  = threadIdx.x;
    const int lane = tid & 31;
    const int w    = tid >> 5;
    const int jb   = blockIdx.x * 8;

    float acc[2][6];
#pragma unroll
    for (int i = 0; i < 2; i++)
#pragma unroll
        for (int c = 0; c < 6; c++) acc[i][c] = 0.0f;

    for (int kt = 0; kt < 16; kt++) {
        const int k0 = kt * 64;
        // load h tile: 64 rows x 64 k = 1024 float4, 8 per thread
#pragma unroll
        for (int r = 0; r < 8; r++) {
            int id  = tid + 128 * r;
            int row = id >> 4;
            int kq  = id & 15;
            float4 v = *(const float4*)(h_in + (size_t)row * DH + k0 + kq * 4);
            ((float4*)hs[row])[kq] = v;
        }
        // load Whh rows: 24 rows x 64 k = 384 float4, 3 per thread
#pragma unroll
        for (int r = 0; r < 3; r++) {
            int id   = tid + 128 * r;
            int c    = id >> 4;      // 0..23
            int kq   = id & 15;
            int jloc = c / 3;
            int g    = c - jloc * 3;
            const float* src = Whh + (size_t)(jb + jloc + g * DH) * DH + k0;
            ((float4*)ws[c])[kq] = *(const float4*)(src + kq * 4);
        }
        __syncthreads();

#pragma unroll
        for (int k4 = 0; k4 < 16; k4++) {
            float4 a0 = ((const float4*)hs[lane])[k4];
            float4 a1 = ((const float4*)hs[lane + 32])[k4];
#pragma unroll
            for (int c = 0; c < 6; c++) {
                float4 wv = ((const float4*)ws[w * 6 + c])[k4];
                acc[0][c] += a0.x * wv.x; acc[0][c] += a0.y * wv.y;
                acc[0][c] += a0.z * wv.z; acc[0][c] += a0.w * wv.w;
                acc[1][c] += a1.x * wv.x; acc[1][c] += a1.y * wv.y;
                acc[1][c] += a1.z * wv.z; acc[1][c] += a1.w * wv.w;
            }
        }
        __syncthreads();
    }

    // fused gate epilogue: warp w's local col cl = jj*3 + g  (jj in {0,1})
#pragma unroll
    for (int i = 0; i < 2; i++) {
        int b = lane + 32 * i;
#pragma unroll
        for (int jj = 0; jj < 2; jj++) {
            int j = jb + w * 2 + jj;
            float ghr = acc[i][jj * 3 + 0] + bhh[j];
            float ghz = acc[i][jj * 3 + 1] + bhh[j + DH];
            float ghn = acc[i][jj * 3 + 2] + bhh[j + 2 * DH];
            size_t base = (size_t)b * H3 + j;
            float gir = gi[base];
            float giz = gi[base + DH];
            float gin = gi[base + 2 * DH];
            if (gi2) {
                gir += gi2[base];
                giz += gi2[base + DH];
                gin += gi2[base + 2 * DH];
            }
            float rr = 1.0f / (1.0f + expf(-(gir + ghr)));
            float zz = 1.0f / (1.0f + expf(-(giz + ghz)));
            float nn = tanhf(gin + rr * ghn);
            float hold = h_in[(size_t)b * DH + j];
            float hv = (1.0f - zz) * nn + zz * hold;
            h_out[(size_t)b * DH + j] = hv;
            if (st_out) st_out[(size_t)b * st_stride + j] = hv;
        }
    }
}

// ===================== launcher =====================

extern "C" void kernel_launch(void* const* d_in, const int* in_sizes, int n_in,
                              void* d_out, int out_size)
{
    const int*   x        = (const int*)d_in[0];
    const int*   labels   = (const int*)d_in[1];
    const int*   bos      = (const int*)d_in[2];
    const float* enc_emb  = (const float*)d_in[3];
    const float* enc_Wih  = (const float*)d_in[4];
    const float* enc_Whh  = (const float*)d_in[5];
    const float* enc_bih  = (const float*)d_in[6];
    const float* enc_bhh  = (const float*)d_in[7];
    const float* dec_emb  = (const float*)d_in[8];
    const float* dec_Wih  = (const float*)d_in[9];
    const float* dec_Whh  = (const float*)d_in[10];
    const float* dec_bih  = (const float*)d_in[11];
    const float* dec_bhh  = (const float*)d_in[12];
    const float* dec_init = (const float*)d_in[13];
    const float* lin_W    = (const float*)d_in[14];
    const float* lin_b    = (const float*)d_in[15];
    float* out = (float*)d_out;

    float *xe, *gi_enc, *wdec, *gi_dec, *gi_ctx, *hA, *hB, *states;
    cudaGetSymbolAddress((void**)&xe,     g_xe);
    cudaGetSymbolAddress((void**)&gi_enc, g_gi_enc);
    cudaGetSymbolAddress((void**)&wdec,   g_wdec);
    cudaGetSymbolAddress((void**)&gi_dec, g_gi_dec);
    cudaGetSymbolAddress((void**)&gi_ctx, g_gi_ctx);
    cudaGetSymbolAddress((void**)&hA,     g_hA);
    cudaGetSymbolAddress((void**)&hB,     g_hB);
    cudaGetSymbolAddress((void**)&states, g_states);

    // ---- encoder ----
    gather_enc<<<TE * BB, 128>>>(x, enc_emb, xe);
    // gi_enc = xe * enc_Wih^T + enc_bih   (8192 x 3072 x 512)
    sgemm_nt<<<dim3(H3 / 128, (TE * BB) / 128), 256>>>(
        xe, enc_Wih, enc_bih, gi_enc, TE * BB, H3, DE, DE, DE);
    set_h<<<64, 1024>>>(hA, nullptr);
    for (int t = 0; t < TE; t++) {
        float* hin  = (t & 1) ? hB : hA;
        float* hout = (t & 1) ? hA : hB;
        gru_step<<<DH / 8, 128>>>(gi_enc + (size_t)t * BB * H3, nullptr,
                                  enc_Whh, enc_bhh, hin, hout, nullptr, 0);
    }
    // encoder final hidden state now in hA (TE even)

    // ---- decoder precompute ----
    gather_dec<<<TD * BB, 128>>>(labels, bos, dec_emb, wdec);
    // word part: gi_dec = wdec * dec_Wih[:, :512]^T + dec_bih   (4096 x 3072 x 512)
    sgemm_nt<<<dim3(H3 / 128, (TD * BB) / 128), 256>>>(
        wdec, dec_Wih, dec_bih, gi_dec, TD * BB, H3, DE, DE, DIN);
    // ctx part (time-invariant): gi_ctx = e_final * dec_Wih[:, 512:]^T   (64 x 3072 x 1024)
    sgemm_nt<<<dim3(H3 / 128, 1), 256>>>(
        hA, dec_Wih + DE, nullptr, gi_ctx, BB, H3, DH, DH, DIN);
    // decoder h0 = broadcast(dec_init); safe to overwrite hA now (ctx GEMM ordered before)
    set_h<<<64, 1024>>>(hA, dec_init);

    // ---- decoder recurrence ----
    for (int t = 0; t < TD; t++) {
        float* hin  = (t & 1) ? hB : hA;
        float* hout = (t & 1) ? hA : hB;
        gru_step<<<DH / 8, 128>>>(gi_dec + (size_t)t * BB * H3, gi_ctx,
                                  dec_Whh, dec_bhh, hin, hout,
                                  states + (size_t)t * DH, TD * DH);
    }

    // ---- output projection: logits = states * lin_W^T + lin_b  (4096 x 32000 x 1024) ----
    sgemm_nt<<<dim3(VV / 128, (TD * BB) / 128), 256>>>(
        states, lin_W, lin_b, out, TD * BB, VV, DH, DH, DH);
}

// round 6
// speedup vs baseline: 1.6501x; 1.6501x over previous
#include <cuda_runtime.h>
#include <math.h>
#include <stdint.h>

// ----- problem constants -----
#define BB 64      // batch
#define TE 128     // encoder timesteps
#define TD 64      // decoder timesteps
#define DE 512     // embedding dim
#define DH 1024    // hidden dim (enc & dec)
#define H3 3072    // 3 * DH
#define VV 32000   // vocab
#define DIN (DE + DH) // decoder input dim = 1536

// ----- scratch (static device globals; no allocation allowed) -----
__device__ float g_xe[(size_t)TE * BB * DE];
__device__ float g_gi_enc[(size_t)TE * BB * H3];
__device__ float g_wdec[(size_t)TD * BB * DE];
__device__ float g_gi_dec[(size_t)TD * BB * H3];
__device__ float g_gi_ctx[(size_t)BB * H3];
__device__ float g_hA[BB * DH];
__device__ float g_hB[BB * DH];
__device__ float g_states[(size_t)BB * TD * DH];  // (B, T_dec, DH) row-major

// ===================== small PTX helpers =====================

__device__ __forceinline__ void cp16(void* s, const void* g) {
    uint32_t sa = (uint32_t)__cvta_generic_to_shared(s);
    asm volatile("cp.async.cg.shared.global [%0], [%1], 16;\n" :: "r"(sa), "l"(g));
}
__device__ __forceinline__ void cp_commit() {
    asm volatile("cp.async.commit_group;\n");
}
template<int N> __device__ __forceinline__ void cp_wait() {
    asm volatile("cp.async.wait_group %0;\n" :: "n"(N));
}
__device__ __forceinline__ uint32_t f2tf(float x) {
    uint32_t r; asm("cvt.rna.tf32.f32 %0, %1;" : "=r"(r) : "f"(x)); return r;
}
__device__ __forceinline__ void mma_tf32(float* d, const uint32_t* a, const uint32_t* b) {
    asm volatile(
        "mma.sync.aligned.m16n8k8.row.col.f32.tf32.tf32.f32 "
        "{%0,%1,%2,%3}, {%4,%5,%6,%7}, {%8,%9}, {%0,%1,%2,%3};\n"
        : "+f"(d[0]), "+f"(d[1]), "+f"(d[2]), "+f"(d[3])
        : "r"(a[0]), "r"(a[1]), "r"(a[2]), "r"(a[3]), "r"(b[0]), "r"(b[1]));
}

// ===================== gather kernels =====================

__global__ void gather_enc(const int* __restrict__ x, const float* __restrict__ emb,
                           float* __restrict__ out)
{
    int r = blockIdx.x;
    int t = r >> 6;
    int b = r & 63;
    int tok = x[b * TE + t];
    const float4* s = (const float4*)(emb + (size_t)tok * DE);
    float4* d = (float4*)(out + (size_t)r * DE);
    d[threadIdx.x] = s[threadIdx.x];
}

__global__ void gather_dec(const int* __restrict__ labels, const int* __restrict__ bos,
                           const float* __restrict__ emb, float* __restrict__ out)
{
    int r = blockIdx.x;
    int t = r >> 6;
    int b = r & 63;
    int tok = (t == 0) ? bos[0] : labels[b * TD + t - 1];
    const float4* s = (const float4*)(emb + (size_t)tok * DE);
    float4* d = (float4*)(out + (size_t)r * DE);
    d[threadIdx.x] = s[threadIdx.x];
}

__global__ void set_h(float* __restrict__ dst, const float* __restrict__ src)
{
    int i = blockIdx.x * 1024 + threadIdx.x;
    dst[i] = src ? src[i & (DH - 1)] : 0.0f;
}

// ===================== fp32 SGEMM-NT (kept for gi / ctx GEMMs: exact) =====================
// C[M,N] = A[M,K](row, lda) * B[N,K](row, ldb)^T + bias[N]

__global__ __launch_bounds__(256) void sgemm_nt(
    const float* __restrict__ A, const float* __restrict__ Bm,
    const float* __restrict__ bias, float* __restrict__ C,
    int M, int N, int K, int lda, int ldb)
{
    __shared__ float As[16][132];
    __shared__ float Bs[16][132];

    const int t  = threadIdx.x;
    const int tx = t & 15;
    const int ty = t >> 4;
    const int row0 = blockIdx.y * 128;
    const int col0 = blockIdx.x * 128;

    float acc[8][8];
#pragma unroll
    for (int i = 0; i < 8; i++)
#pragma unroll
        for (int j = 0; j < 8; j++) acc[i][j] = 0.0f;

    for (int k0 = 0; k0 < K; k0 += 16) {
#pragma unroll
        for (int r = 0; r < 2; r++) {
            int id = t + 256 * r;
            int ar = id >> 2;
            int kq = id & 3;
            float4 v = make_float4(0.f, 0.f, 0.f, 0.f);
            int gr = row0 + ar;
            if (gr < M) v = *(const float4*)(A + (size_t)gr * lda + k0 + kq * 4);
            As[kq * 4 + 0][ar] = v.x;
            As[kq * 4 + 1][ar] = v.y;
            As[kq * 4 + 2][ar] = v.z;
            As[kq * 4 + 3][ar] = v.w;
            float4 wv = *(const float4*)(Bm + (size_t)(col0 + ar) * ldb + k0 + kq * 4);
            Bs[kq * 4 + 0][ar] = wv.x;
            Bs[kq * 4 + 1][ar] = wv.y;
            Bs[kq * 4 + 2][ar] = wv.z;
            Bs[kq * 4 + 3][ar] = wv.w;
        }
        __syncthreads();

#pragma unroll
        for (int k = 0; k < 16; k++) {
            float4 a0 = *(const float4*)&As[k][ty * 4];
            float4 a1 = *(const float4*)&As[k][ty * 4 + 64];
            float4 b0 = *(const float4*)&Bs[k][tx * 4];
            float4 b1 = *(const float4*)&Bs[k][tx * 4 + 64];
            float av[8] = {a0.x, a0.y, a0.z, a0.w, a1.x, a1.y, a1.z, a1.w};
            float bv[8] = {b0.x, b0.y, b0.z, b0.w, b1.x, b1.y, b1.z, b1.w};
#pragma unroll
            for (int i = 0; i < 8; i++)
#pragma unroll
                for (int j = 0; j < 8; j++) acc[i][j] += av[i] * bv[j];
        }
        __syncthreads();
    }

    float bc[8];
#pragma unroll
    for (int j = 0; j < 8; j++) {
        int cj = col0 + ((j < 4) ? (tx * 4 + j) : (64 + tx * 4 + j - 4));
        bc[j] = bias ? bias[cj] : 0.0f;
    }
#pragma unroll
    for (int i = 0; i < 8; i++) {
        int ri = row0 + ((i < 4) ? (ty * 4 + i) : (64 + ty * 4 + i - 4));
        if (ri < M) {
            float4 o0 = make_float4(acc[i][0] + bc[0], acc[i][1] + bc[1],
                                    acc[i][2] + bc[2], acc[i][3] + bc[3]);
            float4 o1 = make_float4(acc[i][4] + bc[4], acc[i][5] + bc[5],
                                    acc[i][6] + bc[6], acc[i][7] + bc[7]);
            *(float4*)(C + (size_t)ri * N + col0 + tx * 4)      = o0;
            *(float4*)(C + (size_t)ri * N + col0 + 64 + tx * 4) = o1;
        }
    }
}

// ===================== tf32 tensor-core GEMM-NT (logits projection) =====================
// C[M,N] = A[M,K] * B[N,K]^T + bias[N].  Requires M%128==0, N%128==0, K%16==0, lda=ldb=K.
// 128x128x16 CTA tile, 8 warps in 4(M)x2(N), warp tile 32x64 via m16n8k8 tf32 mma.
// cp.async 2-stage pipeline; smem [row][20] padding -> conflict-free fragment LDS.

__global__ __launch_bounds__(256) void gemm_tf32_nt(
    const float* __restrict__ A, const float* __restrict__ Bm,
    const float* __restrict__ bias, float* __restrict__ C,
    int M, int N, int K)
{
    __shared__ float As[2][128][20];
    __shared__ float Bs[2][128][20];

    const int tid  = threadIdx.x;
    const int lane = tid & 31;
    const int wid  = tid >> 5;
    const int wm   = wid >> 1;    // 0..3
    const int wn   = wid & 1;     // 0..1
    const int row0 = blockIdx.y * 128;
    const int col0 = blockIdx.x * 128;

    const int lr  = tid >> 2;     // 0..63
    const int lkq = tid & 3;      // 0..3 (float4 slot in k16)

    float d[2][8][4];
#pragma unroll
    for (int mt = 0; mt < 2; mt++)
#pragma unroll
        for (int nt = 0; nt < 8; nt++)
#pragma unroll
            for (int q = 0; q < 4; q++) d[mt][nt][q] = 0.0f;

    const int nk = K / 16;

    auto issue = [&](int kt, int p) {
        int k0 = kt * 16;
#pragma unroll
        for (int r = 0; r < 2; r++) {
            int row = lr + r * 64;
            cp16(&As[p][row][lkq * 4], A  + (size_t)(row0 + row) * K + k0 + lkq * 4);
            cp16(&Bs[p][row][lkq * 4], Bm + (size_t)(col0 + row) * K + k0 + lkq * 4);
        }
    };

    issue(0, 0);
    cp_commit();

    int p = 0;
    for (int kt = 0; kt < nk; kt++) {
        if (kt + 1 < nk) {
            issue(kt + 1, p ^ 1);
            cp_commit();
            cp_wait<1>();
        } else {
            cp_wait<0>();
        }
        __syncthreads();

#pragma unroll
        for (int kk = 0; kk < 2; kk++) {
            int k8 = kk * 8;
            uint32_t af[2][4], bf[8][2];
#pragma unroll
            for (int mt = 0; mt < 2; mt++) {
                int mb = wm * 32 + mt * 16;
                af[mt][0] = f2tf(As[p][mb +     (lane >> 2)][k8 +     (lane & 3)]);
                af[mt][1] = f2tf(As[p][mb + 8 + (lane >> 2)][k8 +     (lane & 3)]);
                af[mt][2] = f2tf(As[p][mb +     (lane >> 2)][k8 + 4 + (lane & 3)]);
                af[mt][3] = f2tf(As[p][mb + 8 + (lane >> 2)][k8 + 4 + (lane & 3)]);
            }
#pragma unroll
            for (int nt = 0; nt < 8; nt++) {
                int nb = wn * 64 + nt * 8;
                bf[nt][0] = f2tf(Bs[p][nb + (lane >> 2)][k8 +     (lane & 3)]);
                bf[nt][1] = f2tf(Bs[p][nb + (lane >> 2)][k8 + 4 + (lane & 3)]);
            }
#pragma unroll
            for (int mt = 0; mt < 2; mt++)
#pragma unroll
                for (int nt = 0; nt < 8; nt++)
                    mma_tf32(d[mt][nt], af[mt], bf[nt]);
        }
        __syncthreads();
        p ^= 1;
    }

    // epilogue: d0,d1 -> (r, c),(r, c+1); d2,d3 -> (r+8, c),(r+8, c+1)
#pragma unroll
    for (int mt = 0; mt < 2; mt++) {
        int r0 = row0 + wm * 32 + mt * 16 + (lane >> 2);
#pragma unroll
        for (int nt = 0; nt < 8; nt++) {
            int c = col0 + wn * 64 + nt * 8 + (lane & 3) * 2;
            float b0v = bias ? bias[c] : 0.0f;
            float b1v = bias ? bias[c + 1] : 0.0f;
            float2 o0 = make_float2(d[mt][nt][0] + b0v, d[mt][nt][1] + b1v);
            float2 o1 = make_float2(d[mt][nt][2] + b0v, d[mt][nt][3] + b1v);
            *(float2*)(C + (size_t)r0 * N + c)       = o0;
            *(float2*)(C + (size_t)(r0 + 8) * N + c) = o1;
        }
    }
}

// ===================== fused GRU step (v2: 8 warps + cp.async pipeline) =====================
// grid = DH/8 = 128 CTAs, 256 threads (8 warps). CTA owns 8 hidden cols j (24 Whh rows);
// warp w owns j = jb + w (its 3 gate rows -> pure smem broadcast reads).
// Lane owns batches (lane, lane+32). Double-buffered h/W tiles overlap loads with FMA.

__global__ __launch_bounds__(256) void gru_step(
    const float* __restrict__ gi,    // (B,H3) input-gate preactivations (incl. bih)
    const float* __restrict__ gi2,   // optional second term (decoder ctx), or nullptr
    const float* __restrict__ Whh,   // (H3, DH) row-major
    const float* __restrict__ bhh,   // (H3)
    const float* __restrict__ h_in,  // (B, DH)
    float* __restrict__ h_out,       // (B, DH)
    float* __restrict__ st_out,      // optional: states base + t*DH
    int st_stride)
{
    __shared__ float hs[2][64][68];   // 34816 B
    __shared__ float ws[2][24][68];   // 13056 B  (total 47872 <= 48K static)

    const int tid  = threadIdx.x;
    const int lane = tid & 31;
    const int w    = tid >> 5;        // 0..7
    const int jb   = blockIdx.x * 8;

    float acc[2][3];
#pragma unroll
    for (int i = 0; i < 2; i++)
#pragma unroll
        for (int g = 0; g < 3; g++) acc[i][g] = 0.0f;

    auto issue = [&](int kt, int p) {
        const int k0 = kt * 64;
        // h tile: 64 rows x 64 k = 1024 float4 -> 4 per thread
#pragma unroll
        for (int r = 0; r < 4; r++) {
            int id  = tid + 256 * r;
            int row = id >> 4;
            int kq  = id & 15;
            cp16(&hs[p][row][kq * 4], h_in + (size_t)row * DH + k0 + kq * 4);
        }
        // Whh rows: 24 x 16 float4 = 384 -> threads 0..255 do 1, 0..127 do one more
        {
            int c  = tid >> 4;                 // 0..15
            int kq = tid & 15;
            int jloc = c / 3, g = c - jloc * 3;
            cp16(&ws[p][c][kq * 4],
                 Whh + (size_t)(jb + jloc + g * DH) * DH + k0 + kq * 4);
        }
        if (tid < 128) {
            int id = tid + 256;
            int c  = id >> 4;                  // 16..23
            int kq = id & 15;
            int jloc = c / 3, g = c - jloc * 3;
            cp16(&ws[p][c][kq * 4],
                 Whh + (size_t)(jb + jloc + g * DH) * DH + k0 + kq * 4);
        }
    };

    issue(0, 0);
    cp_commit();

    int p = 0;
    for (int kt = 0; kt < 16; kt++) {
        if (kt < 15) {
            issue(kt + 1, p ^ 1);
            cp_commit();
            cp_wait<1>();
        } else {
            cp_wait<0>();
        }
        __syncthreads();

#pragma unroll
        for (int k4 = 0; k4 < 16; k4++) {
            float4 a0 = ((const float4*)hs[p][lane])[k4];
            float4 a1 = ((const float4*)hs[p][lane + 32])[k4];
#pragma unroll
            for (int g = 0; g < 3; g++) {
                float4 wv = ((const float4*)ws[p][w * 3 + g])[k4];
                acc[0][g] += a0.x * wv.x; acc[0][g] += a0.y * wv.y;
                acc[0][g] += a0.z * wv.z; acc[0][g] += a0.w * wv.w;
                acc[1][g] += a1.x * wv.x; acc[1][g] += a1.y * wv.y;
                acc[1][g] += a1.z * wv.z; acc[1][g] += a1.w * wv.w;
            }
        }
        __syncthreads();
        p ^= 1;
    }

    // fused gate epilogue: warp w -> hidden column j = jb + w
    const int j = jb + w;
    const float bh_r = bhh[j];
    const float bh_z = bhh[j + DH];
    const float bh_n = bhh[j + 2 * DH];
#pragma unroll
    for (int i = 0; i < 2; i++) {
        int b = lane + 32 * i;
        size_t base = (size_t)b * H3 + j;
        float gir = gi[base];
        float giz = gi[base + DH];
        float gin = gi[base + 2 * DH];
        if (gi2) {
            gir += gi2[base];
            giz += gi2[base + DH];
            gin += gi2[base + 2 * DH];
        }
        float rr = 1.0f / (1.0f + expf(-(gir + acc[i][0] + bh_r)));
        float zz = 1.0f / (1.0f + expf(-(giz + acc[i][1] + bh_z)));
        float hn = acc[i][2] + bh_n;
        float nn = tanhf(gin + rr * hn);
        float hold = h_in[(size_t)b * DH + j];
        float hv = (1.0f - zz) * nn + zz * hold;
        h_out[(size_t)b * DH + j] = hv;
        if (st_out) st_out[(size_t)b * st_stride + j] = hv;
    }
}

// ===================== launcher =====================

extern "C" void kernel_launch(void* const* d_in, const int* in_sizes, int n_in,
                              void* d_out, int out_size)
{
    const int*   x        = (const int*)d_in[0];
    const int*   labels   = (const int*)d_in[1];
    const int*   bos      = (const int*)d_in[2];
    const float* enc_emb  = (const float*)d_in[3];
    const float* enc_Wih  = (const float*)d_in[4];
    const float* enc_Whh  = (const float*)d_in[5];
    const float* enc_bih  = (const float*)d_in[6];
    const float* enc_bhh  = (const float*)d_in[7];
    const float* dec_emb  = (const float*)d_in[8];
    const float* dec_Wih  = (const float*)d_in[9];
    const float* dec_Whh  = (const float*)d_in[10];
    const float* dec_bih  = (const float*)d_in[11];
    const float* dec_bhh  = (const float*)d_in[12];
    const float* dec_init = (const float*)d_in[13];
    const float* lin_W    = (const float*)d_in[14];
    const float* lin_b    = (const float*)d_in[15];
    float* out = (float*)d_out;

    float *xe, *gi_enc, *wdec, *gi_dec, *gi_ctx, *hA, *hB, *states;
    cudaGetSymbolAddress((void**)&xe,     g_xe);
    cudaGetSymbolAddress((void**)&gi_enc, g_gi_enc);
    cudaGetSymbolAddress((void**)&wdec,   g_wdec);
    cudaGetSymbolAddress((void**)&gi_dec, g_gi_dec);
    cudaGetSymbolAddress((void**)&gi_ctx, g_gi_ctx);
    cudaGetSymbolAddress((void**)&hA,     g_hA);
    cudaGetSymbolAddress((void**)&hB,     g_hB);
    cudaGetSymbolAddress((void**)&states, g_states);

    // ---- encoder ----
    gather_enc<<<TE * BB, 128>>>(x, enc_emb, xe);
    sgemm_nt<<<dim3(H3 / 128, (TE * BB) / 128), 256>>>(
        xe, enc_Wih, enc_bih, gi_enc, TE * BB, H3, DE, DE, DE);
    set_h<<<64, 1024>>>(hA, nullptr);
    for (int t = 0; t < TE; t++) {
        float* hin  = (t & 1) ? hB : hA;
        float* hout = (t & 1) ? hA : hB;
        gru_step<<<DH / 8, 256>>>(gi_enc + (size_t)t * BB * H3, nullptr,
                                  enc_Whh, enc_bhh, hin, hout, nullptr, 0);
    }
    // encoder final hidden state now in hA (TE even)

    // ---- decoder precompute ----
    gather_dec<<<TD * BB, 128>>>(labels, bos, dec_emb, wdec);
    sgemm_nt<<<dim3(H3 / 128, (TD * BB) / 128), 256>>>(
        wdec, dec_Wih, dec_bih, gi_dec, TD * BB, H3, DE, DE, DIN);
    sgemm_nt<<<dim3(H3 / 128, 1), 256>>>(
        hA, dec_Wih + DE, nullptr, gi_ctx, BB, H3, DH, DH, DIN);
    set_h<<<64, 1024>>>(hA, dec_init);

    // ---- decoder recurrence ----
    for (int t = 0; t < TD; t++) {
        float* hin  = (t & 1) ? hB : hA;
        float* hout = (t & 1) ? hA : hB;
        gru_step<<<DH / 8, 256>>>(gi_dec + (size_t)t * BB * H3, gi_ctx,
                                  dec_Whh, dec_bhh, hin, hout,
                                  states + (size_t)t * DH, TD * DH);
    }

    // ---- output projection (tf32 tensor cores): logits = states * lin_W^T + lin_b ----
    gemm_tf32_nt<<<dim3(VV / 128, (TD * BB) / 128), 256>>>(
        states, lin_W, lin_b, out, TD * BB, VV, DH);
}